// round 12
// baseline (speedup 1.0000x reference)
#include <cuda_runtime.h>

// Depthwise 3x3 lateral conv (center tap excluded) + residual, NHWC f32.
// x: [32,56,56,256], kernel: [3,3,256], out: [32,56,56,256]
//
// R12: perfectly balanced persistent strips. 6272 tiles = 448 blocks x 14
// tiles exactly: one block per (yb, b) strip, walking xb=0..13 along w.
// All 448 blocks resident in a single wave (<=4 CTAs/SM). Per-strip the
// h-edge branch is hoisted (fixed per block); only xb=0/13 take the
// w-guarded path, the 12 interior tiles run pure immediate-offset loads.
// Consecutive tiles share 2 halo columns -> L1 hits. Tile math as R8/R11:
// HR=4 x WR=4 float2, taps in registers, residual folded as center add.

#define H 56
#define W 56
#define C2 128        // channels as float2
#define HR 4
#define WR 4
#define TX (W / WR)   // 14
#define TY (H / HR)   // 14
#define NBLOCKS (TY * 32)  // 448: one strip per (yb, b)

__device__ __forceinline__ void f2fma(float2& a, float2 v, float2 k) {
    a.x = fmaf(v.x, k.x, a.x);
    a.y = fmaf(v.y, k.y, a.y);
}

// One HR x WR tile. HE: h-edge guards needed; WE: w-edge guards needed.
template<bool HE, bool WE>
__device__ __forceinline__ void do_tile(
    const float2* __restrict__ xin, float2* __restrict__ o,
    const float2 kreg[8], int img, int hb, int wb, int c2)
{
    float2 acc[HR][WR];
    #pragma unroll
    for (int r = 0; r < HR; r++)
        #pragma unroll
        for (int j = 0; j < WR; j++)
            acc[r][j] = make_float2(0.f, 0.f);

    const float2* __restrict__ p =
        xin + img + ((hb - 1) * W + (wb - 1)) * C2 + c2;

    #pragma unroll
    for (int ih = 0; ih < HR + 2; ih++) {
        bool rowok = true;
        if (HE) {
            const int row = hb - 1 + ih;
            rowok = ((unsigned)row < (unsigned)H);
        }

        float2 v[WR + 2];
        #pragma unroll
        for (int j = 0; j < WR + 2; j++) {
            bool ok = rowok;
            if (WE) {
                const int col = wb - 1 + j;
                ok = ok && ((unsigned)col < (unsigned)W);
            }
            v[j] = ok ? p[(ih * W + j) * C2] : make_float2(0.f, 0.f);
        }

        #pragma unroll
        for (int r = 0; r < HR; r++) {
            const int kh = ih - r;
            if (kh < 0 || kh > 2) continue;
            #pragma unroll
            for (int dw = 0; dw < 3; dw++) {
                const bool is_center = (kh == 1 && dw == 1);
                const int lin = kh * 3 + dw;
                const int t = lin - (lin > 4 ? 1 : 0);
                #pragma unroll
                for (int j = 0; j < WR; j++) {
                    if (is_center) {
                        acc[r][j].x += v[j + 1].x;   // residual
                        acc[r][j].y += v[j + 1].y;
                    } else {
                        f2fma(acc[r][j], v[j + dw], kreg[t]);
                    }
                }
            }
        }
    }

    #pragma unroll
    for (int r = 0; r < HR; r++) {
        const int rb = img + (hb + r) * (W * C2) + c2;
        #pragma unroll
        for (int j = 0; j < WR; j++)
            o[rb + (wb + j) * C2] = acc[r][j];
    }
}

__global__ __launch_bounds__(128, 4) void contour_kernel(
    const float* __restrict__ x,
    const float* __restrict__ kern,
    float* __restrict__ out)
{
    const int c2 = threadIdx.x;              // 0..127 (2 channels)
    const int yb = blockIdx.x % TY;          // strip row
    const int b  = blockIdx.x / TY;          // batch
    const int hb = yb * HR;
    const int img = b * (H * W * C2);

    const float2* __restrict__ xin = reinterpret_cast<const float2*>(x);
    const float2* __restrict__ k2  = reinterpret_cast<const float2*>(kern);
    float2* __restrict__ o = reinterpret_cast<float2*>(out);

    // taps -> registers once per strip (c2 invariant across 14 tiles)
    float2 kreg[8];
    #pragma unroll
    for (int t = 0; t < 8; t++) {
        const int tap = t + (t >= 4 ? 1 : 0);
        kreg[t] = k2[tap * C2 + c2];
    }

    if (yb >= 1 && yb <= TY - 2) {
        // h-interior strip
        do_tile<false, true>(xin, o, kreg, img, hb, 0, c2);
        #pragma unroll 1
        for (int xb = 1; xb <= TX - 2; xb++)
            do_tile<false, false>(xin, o, kreg, img, hb, xb * WR, c2);
        do_tile<false, true>(xin, o, kreg, img, hb, (TX - 1) * WR, c2);
    } else {
        // top/bottom edge strip
        do_tile<true, true>(xin, o, kreg, img, hb, 0, c2);
        #pragma unroll 1
        for (int xb = 1; xb <= TX - 2; xb++)
            do_tile<true, false>(xin, o, kreg, img, hb, xb * WR, c2);
        do_tile<true, true>(xin, o, kreg, img, hb, (TX - 1) * WR, c2);
    }
}

extern "C" void kernel_launch(void* const* d_in, const int* in_sizes, int n_in,
                              void* d_out, int out_size)
{
    const float* x    = (const float*)d_in[0];   // [32,56,56,256]
    const float* kern = (const float*)d_in[1];   // [3,3,256]
    float* outp       = (float*)d_out;

    dim3 block(C2, 1, 1);            // 128 threads
    dim3 grid(NBLOCKS, 1, 1);        // 448 strips, exactly 14 tiles each
    contour_kernel<<<grid, block>>>(x, kern, outp);
}